// round 1
// baseline (speedup 1.0000x reference)
#include <cuda_runtime.h>
#include <cuda_bf16.h>
#include <cstdint>

// Problem constants
#define SEQ   4096
#define DMODEL 1024
#define D3    3072
#define NHEAD 16
#define HDIM  64
#define WIN   512
#define NCHUNK 8

// Scratch (device globals: allocation-free per harness rules)
__device__ float g_qkv[SEQ * D3];        // 48 MB
__device__ float g_attn[SEQ * DMODEL];   // 16 MB

// ---------------------------------------------------------------------------
// Classic 128x128x8 register-blocked SGEMM. A[M,K], B[K,N], C[M,N] row-major.
// All dims divisible by tile sizes for this problem (no bounds checks).
// ---------------------------------------------------------------------------
__global__ __launch_bounds__(256) void sgemm128(const float* __restrict__ A,
                                                const float* __restrict__ B,
                                                float* __restrict__ C,
                                                int M, int N, int K) {
    constexpr int BM = 128, BN = 128, BK = 8, TM = 8, TN = 8;
    __shared__ __align__(16) float As[BK][BM];   // transposed A tile
    __shared__ __align__(16) float Bs[BK][BN];

    const int brow = blockIdx.y, bcol = blockIdx.x;
    const int tid = threadIdx.x;
    const int trow = tid / 16;   // 0..15
    const int tcol = tid % 16;   // 0..15

    const int a_row = tid >> 1;          // 0..127
    const int a_col = (tid & 1) * 4;     // 0 or 4
    const int b_row = tid >> 5;          // 0..7
    const int b_col = (tid & 31) * 4;    // 0..124

    const float* Ab = A + (size_t)brow * BM * K;
    const float* Bb = B + bcol * BN;

    float acc[TM][TN] = {};
    for (int k0 = 0; k0 < K; k0 += BK) {
        float4 av = *(const float4*)(Ab + (size_t)a_row * K + k0 + a_col);
        As[a_col + 0][a_row] = av.x;
        As[a_col + 1][a_row] = av.y;
        As[a_col + 2][a_row] = av.z;
        As[a_col + 3][a_row] = av.w;
        float4 bv = *(const float4*)(Bb + (size_t)(k0 + b_row) * N + b_col);
        *(float4*)&Bs[b_row][b_col] = bv;
        __syncthreads();

        #pragma unroll
        for (int kk = 0; kk < BK; kk++) {
            float ar[TM], br[TN];
            float4 a0 = *(const float4*)&As[kk][trow * TM];
            float4 a1 = *(const float4*)&As[kk][trow * TM + 4];
            ar[0]=a0.x; ar[1]=a0.y; ar[2]=a0.z; ar[3]=a0.w;
            ar[4]=a1.x; ar[5]=a1.y; ar[6]=a1.z; ar[7]=a1.w;
            float4 b0 = *(const float4*)&Bs[kk][tcol * TN];
            float4 b1 = *(const float4*)&Bs[kk][tcol * TN + 4];
            br[0]=b0.x; br[1]=b0.y; br[2]=b0.z; br[3]=b0.w;
            br[4]=b1.x; br[5]=b1.y; br[6]=b1.z; br[7]=b1.w;
            #pragma unroll
            for (int i = 0; i < TM; i++)
                #pragma unroll
                for (int j = 0; j < TN; j++)
                    acc[i][j] += ar[i] * br[j];
        }
        __syncthreads();
    }

    float* Cb = C + (size_t)brow * BM * N + bcol * BN;
    #pragma unroll
    for (int i = 0; i < TM; i++)
        #pragma unroll
        for (int j = 0; j < TN; j += 4) {
            float4 v = make_float4(acc[i][j], acc[i][j+1], acc[i][j+2], acc[i][j+3]);
            *(float4*)(Cb + (size_t)(trow * TM + i) * N + tcol * TN + j) = v;
        }
}

// ---------------------------------------------------------------------------
// Sliding-window attention, flash-style online softmax, fp32.
// Block = (q-tile of 64, chunk c, head h). Keys stream in 64-wide blocks
// drawn from chunks [c-1, c] (window index j in [0, 2W)).
// ---------------------------------------------------------------------------
struct AttnSmem {
    float Qs[64][65];   // [d][q] transposed
    float Ks[64][65];   // [d][j] transposed
    float Vs[64][64];   // [j][d]
    float Ss[64][68];   // [j][q] scores -> probabilities (padded)
    float m_s[64], l_s[64], alpha_s[64];
};

__global__ __launch_bounds__(256) void attn_kernel(const float* __restrict__ qkv,
                                                   float* __restrict__ out) {
    extern __shared__ char smem_raw[];
    AttnSmem& sm = *reinterpret_cast<AttnSmem*>(smem_raw);

    const int qt = blockIdx.x;   // 0..7  (64-query tile within chunk)
    const int c  = blockIdx.y;   // 0..7
    const int h  = blockIdx.z;   // 0..15
    const int tid = threadIdx.x;
    const int tx = tid % 16, ty = tid / 16;

    const int q0 = qt * 64;
    const int qbase_row = c * WIN + q0;

    // Load Q tile transposed: Qs[d][q]
    {
        const int q = tid >> 2;
        const float* src = qkv + (size_t)(qbase_row + q) * D3 + h * HDIM;
        #pragma unroll
        for (int i = 0; i < 4; i++) {
            int cd = (tid & 3) + i * 4;   // float4 chunk 0..15
            float4 v = *(const float4*)(src + cd * 4);
            sm.Qs[cd*4+0][q] = v.x; sm.Qs[cd*4+1][q] = v.y;
            sm.Qs[cd*4+2][q] = v.z; sm.Qs[cd*4+3][q] = v.w;
        }
    }
    if (tid < 64) { sm.m_s[tid] = -1e30f; sm.l_s[tid] = 0.f; }

    float o[4][4] = {};
    const int kb_start = (c == 0) ? (WIN / 64) : 0;
    const int kb_end = ((q0 + 63 + WIN) >> 6) + 1;   // exclusive, <= 16

    for (int kb = kb_start; kb < kb_end; kb++) {
        const int j0 = kb * 64;
        __syncthreads();  // protect Ks/Vs/Ss reuse (and first-iter Q/m init)

        // Load K (transposed) and V (natural)
        {
            const int j = tid >> 2;
            const int krow = c * WIN + j0 - WIN + j;   // global seq position
            const float* ksrc = qkv + (size_t)krow * D3 + DMODEL + h * HDIM;
            const float* vsrc = qkv + (size_t)krow * D3 + 2 * DMODEL + h * HDIM;
            #pragma unroll
            for (int i = 0; i < 4; i++) {
                int cd = (tid & 3) + i * 4;
                float4 kv = *(const float4*)(ksrc + cd * 4);
                sm.Ks[cd*4+0][j] = kv.x; sm.Ks[cd*4+1][j] = kv.y;
                sm.Ks[cd*4+2][j] = kv.z; sm.Ks[cd*4+3][j] = kv.w;
                float4 vv = *(const float4*)(vsrc + cd * 4);
                *(float4*)&sm.Vs[j][cd * 4] = vv;
            }
        }
        __syncthreads();

        // S = Q K^T  (64x64x64), thread owns 4 queries x 4 keys
        float s[4][4] = {};
        #pragma unroll 8
        for (int d = 0; d < 64; d++) {
            float qr[4], kr[4];
            #pragma unroll
            for (int i = 0; i < 4; i++) qr[i] = sm.Qs[d][ty * 4 + i];
            #pragma unroll
            for (int j = 0; j < 4; j++) kr[j] = sm.Ks[d][tx * 4 + j];
            #pragma unroll
            for (int i = 0; i < 4; i++)
                #pragma unroll
                for (int j = 0; j < 4; j++) s[i][j] += qr[i] * kr[j];
        }
        // mask + scale, write Ss[j][q]
        #pragma unroll
        for (int i = 0; i < 4; i++)
            #pragma unroll
            for (int j = 0; j < 4; j++) {
                int qg = q0 + ty * 4 + i;          // query pos within chunk
                int jg = j0 + tx * 4 + j;          // key pos within 2W window
                float val = (qg + WIN >= jg) ? s[i][j] * 0.125f : -1e30f;
                sm.Ss[tx * 4 + j][ty * 4 + i] = val;
            }
        __syncthreads();

        // Online softmax stats: 4 threads per query (contiguous lanes)
        {
            const int q = tid >> 2;
            const int r = tid & 3;
            float mx = -1e30f;
            #pragma unroll
            for (int t = 0; t < 16; t++) mx = fmaxf(mx, sm.Ss[r * 16 + t][q]);
            mx = fmaxf(mx, __shfl_xor_sync(0xffffffffu, mx, 1));
            mx = fmaxf(mx, __shfl_xor_sync(0xffffffffu, mx, 2));
            const float m_old = sm.m_s[q];
            const float m_new = fmaxf(m_old, mx);
            float sum = 0.f;
            #pragma unroll
            for (int t = 0; t < 16; t++) {
                float p = __expf(sm.Ss[r * 16 + t][q] - m_new);
                sm.Ss[r * 16 + t][q] = p;
                sum += p;
            }
            sum += __shfl_xor_sync(0xffffffffu, sum, 1);
            sum += __shfl_xor_sync(0xffffffffu, sum, 2);
            if (r == 0) {
                float alpha = __expf(m_old - m_new);
                sm.m_s[q] = m_new;
                sm.l_s[q] = sm.l_s[q] * alpha + sum;
                sm.alpha_s[q] = alpha;
            }
        }
        __syncthreads();

        // O = O*alpha + P V  (64x64x64), thread owns 4 queries x 4 dims
        #pragma unroll
        for (int i = 0; i < 4; i++) {
            float a = sm.alpha_s[ty * 4 + i];
            #pragma unroll
            for (int j = 0; j < 4; j++) o[i][j] *= a;
        }
        #pragma unroll 4
        for (int k = 0; k < 64; k++) {
            float pr[4], vr[4];
            #pragma unroll
            for (int i = 0; i < 4; i++) pr[i] = sm.Ss[k][ty * 4 + i];
            #pragma unroll
            for (int j = 0; j < 4; j++) vr[j] = sm.Vs[k][tx * 4 + j];
            #pragma unroll
            for (int i = 0; i < 4; i++)
                #pragma unroll
                for (int j = 0; j < 4; j++) o[i][j] += pr[i] * vr[j];
        }
    }

    // Finalize: divide by l, write [s, h*HDIM + d] layout
    #pragma unroll
    for (int i = 0; i < 4; i++) {
        const int q = ty * 4 + i;
        const float inv = 1.f / sm.l_s[q];
        float4 v = make_float4(o[i][0] * inv, o[i][1] * inv,
                               o[i][2] * inv, o[i][3] * inv);
        *(float4*)(out + (size_t)(qbase_row + q) * DMODEL + h * HDIM + tx * 4) = v;
    }
}

// ---------------------------------------------------------------------------
extern "C" void kernel_launch(void* const* d_in, const int* in_sizes, int n_in,
                              void* d_out, int out_size) {
    const float* x      = (const float*)d_in[0];   // [4096,1024]
    const float* w_qkv  = (const float*)d_in[1];   // [1024,3072]
    const float* w_out  = (const float*)d_in[2];   // [1024,1024]
    float* out = (float*)d_out;                    // [4096,1024]

    float *qkv, *attn;
    cudaGetSymbolAddress((void**)&qkv, g_qkv);
    cudaGetSymbolAddress((void**)&attn, g_attn);

    cudaFuncSetAttribute(attn_kernel, cudaFuncAttributeMaxDynamicSharedMemorySize,
                         (int)sizeof(AttnSmem));

    // 1) qkv = x @ w_qkv
    sgemm128<<<dim3(D3 / 128, SEQ / 128), 256>>>(x, w_qkv, qkv, SEQ, D3, DMODEL);
    // 2) sliding-window attention
    attn_kernel<<<dim3(8, NCHUNK, NHEAD), 256, sizeof(AttnSmem)>>>(qkv, attn);
    // 3) out = attn @ w_out
    sgemm128<<<dim3(DMODEL / 128, SEQ / 128), 256>>>(attn, w_out, out, SEQ, DMODEL, DMODEL);
}

// round 2
// speedup vs baseline: 1.2037x; 1.2037x over previous
#include <cuda_runtime.h>
#include <cuda_bf16.h>
#include <cstdint>

// Problem constants
#define SEQ    4096
#define DMODEL 1024
#define D3     3072
#define NHEAD  16
#define HDIM   64
#define WIN    512
#define NCHUNK 8

// Scratch (device globals: allocation-free per harness rules)
__device__ float g_qkv[SEQ * D3];        // 48 MB
__device__ float g_attn[SEQ * DMODEL];   // 16 MB

// ---------------------------------------------------------------------------
// tf32 helpers
// ---------------------------------------------------------------------------
__device__ __forceinline__ uint32_t f2tf32(float x) {
    uint32_t r;
    asm("cvt.rna.tf32.f32 %0, %1;" : "=r"(r) : "f"(x));
    return r;
}
__device__ __forceinline__ void split_tf32(float x, uint32_t& hi, uint32_t& lo) {
    hi = f2tf32(x);
    float l = x - __uint_as_float(hi);   // exact (Dekker split)
    lo = f2tf32(l);
}

#define MMA_TF32(d, a0, a1, a2, a3, b0, b1)                                    \
    asm volatile(                                                              \
        "mma.sync.aligned.m16n8k8.row.col.f32.tf32.tf32.f32 "                  \
        "{%0,%1,%2,%3}, {%4,%5,%6,%7}, {%8,%9}, {%0,%1,%2,%3};"                \
        : "+f"((d)[0]), "+f"((d)[1]), "+f"((d)[2]), "+f"((d)[3])               \
        : "r"(a0), "r"(a1), "r"(a2), "r"(a3), "r"(b0), "r"(b1))

#define LDSM_X4(r0, r1, r2, r3, addr)                                          \
    asm volatile("ldmatrix.sync.aligned.m8n8.x4.shared.b16 {%0,%1,%2,%3}, [%4];" \
        : "=r"(r0), "=r"(r1), "=r"(r2), "=r"(r3) : "r"(addr))

// ---------------------------------------------------------------------------
// 3xTF32 GEMM, 128x128 CTA tile, BK=32, 256 threads (8 warps: 2m x 4n).
// A[M,K] row-major, B[K,N] row-major, C[M,N] row-major. Dims % tile == 0.
// Smem: Ah/Al as swizzled [m][k] (32 floats/row, 16B-chunk XOR swizzle),
//       Bh/Bl as [k][n] with pad (row = 132 floats).
// ---------------------------------------------------------------------------
// u32-offset layout inside dynamic smem:
#define SM_AH 0
#define SM_AL 4096
#define SM_BH 8192
#define SM_BL (8192 + 4224)
#define SM_TOTAL_U32 (8192 + 2 * 4224)   // 16640 u32 = 66560 B

__global__ __launch_bounds__(256) void gemm_3xtf32(const float* __restrict__ A,
                                                   const float* __restrict__ B,
                                                   float* __restrict__ C,
                                                   int M, int N, int K) {
    extern __shared__ uint32_t sm[];
    uint32_t* __restrict__ Ah = sm + SM_AH;
    uint32_t* __restrict__ Al = sm + SM_AL;
    uint32_t* __restrict__ Bh = sm + SM_BH;
    uint32_t* __restrict__ Bl = sm + SM_BL;

    const int tid  = threadIdx.x;
    const int lane = tid & 31;
    const int warp = tid >> 5;
    const int warp_m = warp >> 2;        // 0..1
    const int warp_n = warp & 3;         // 0..3

    const int m0 = blockIdx.y * 128;
    const int n0 = blockIdx.x * 128;

    // A loader indices: thread covers 4 rows (m = tid/8 + 32r), chunk = tid%8
    const int a_m_base = tid >> 3;       // 0..31
    const int a_kc     = tid & 7;        // 16B chunk within 32-float row
    // B loader indices: thread covers 4 k-rows (k = tid/32 + 8r), n4 = tid%32
    const int b_n4 = tid & 31;           // float4 col: n = b_n4*4
    const int b_k  = tid >> 5;           // 0..7

    // ldmatrix per-lane addressing (within a 16x8 fragment)
    const int lm_row  = (lane & 7) + ((lane >> 3) & 1) * 8;  // 0..15
    const int lm_csel = lane >> 4;                            // chunk select 0/1

    // B fragment per-lane indices
    const int bf_n = lane >> 2;          // 0..7
    const int bf_k = lane & 3;           // 0..3

    float acc[4][4][4] = {};

    const uint32_t ah_base = (uint32_t)__cvta_generic_to_shared(Ah);
    const uint32_t al_base = (uint32_t)__cvta_generic_to_shared(Al);

    for (int k0 = 0; k0 < K; k0 += 32) {
        // ---- load + split A tile (128 x 32) ----
        #pragma unroll
        for (int r = 0; r < 4; r++) {
            const int m = a_m_base + 32 * r;
            const float4 v = *(const float4*)(A + (size_t)(m0 + m) * K + k0 + a_kc * 4);
            uint4 h, l;
            split_tf32(v.x, h.x, l.x);
            split_tf32(v.y, h.y, l.y);
            split_tf32(v.z, h.z, l.z);
            split_tf32(v.w, h.w, l.w);
            const int off = m * 32 + ((a_kc ^ (m & 7)) << 2);
            *(uint4*)&Ah[off] = h;
            *(uint4*)&Al[off] = l;
        }
        // ---- load + split B tile (32 x 128) ----
        #pragma unroll
        for (int r = 0; r < 4; r++) {
            const int k = b_k + 8 * r;
            const float4 v = *(const float4*)(B + (size_t)(k0 + k) * N + n0 + b_n4 * 4);
            uint4 h, l;
            split_tf32(v.x, h.x, l.x);
            split_tf32(v.y, h.y, l.y);
            split_tf32(v.z, h.z, l.z);
            split_tf32(v.w, h.w, l.w);
            const int off = k * 132 + b_n4 * 4;
            *(uint4*)&Bh[off] = h;
            *(uint4*)&Bl[off] = l;
        }
        __syncthreads();

        // ---- compute: 4 k8-steps ----
        #pragma unroll
        for (int k8 = 0; k8 < 4; k8++) {
            const int c0 = k8 * 2;  // first 16B chunk of this k8 slice

            // Load A fragments (hi & lo) for 4 m-frags via ldmatrix.x4
            uint32_t aH[4][4], aL[4][4];
            #pragma unroll
            for (int mf = 0; mf < 4; mf++) {
                const int m = warp_m * 64 + mf * 16 + lm_row;
                const uint32_t foff =
                    4u * (m * 32 + (((c0 + lm_csel) ^ (m & 7)) << 2));
                LDSM_X4(aH[mf][0], aH[mf][1], aH[mf][2], aH[mf][3], ah_base + foff);
                LDSM_X4(aL[mf][0], aL[mf][1], aL[mf][2], aL[mf][3], al_base + foff);
            }

            const int kk = k8 * 8;
            #pragma unroll
            for (int nf = 0; nf < 4; nf++) {
                const int n = warp_n * 32 + nf * 8 + bf_n;
                const int r0 = (kk + bf_k) * 132 + n;
                const int r1 = r0 + 4 * 132;
                const uint32_t bh0 = Bh[r0], bh1 = Bh[r1];
                const uint32_t bl0 = Bl[r0], bl1 = Bl[r1];
                #pragma unroll
                for (int mf = 0; mf < 4; mf++) {
                    MMA_TF32(acc[mf][nf], aH[mf][0], aH[mf][1], aH[mf][2], aH[mf][3], bh0, bh1);
                    MMA_TF32(acc[mf][nf], aH[mf][0], aH[mf][1], aH[mf][2], aH[mf][3], bl0, bl1);
                    MMA_TF32(acc[mf][nf], aL[mf][0], aL[mf][1], aL[mf][2], aL[mf][3], bh0, bh1);
                }
            }
        }
        __syncthreads();
    }

    // ---- epilogue ----
    const int row_in = lane >> 2;        // 0..7
    const int col_in = 2 * (lane & 3);   // 0,2,4,6
    #pragma unroll
    for (int mf = 0; mf < 4; mf++) {
        const int gr = m0 + warp_m * 64 + mf * 16 + row_in;
        #pragma unroll
        for (int nf = 0; nf < 4; nf++) {
            const int gc = n0 + warp_n * 32 + nf * 8 + col_in;
            *(float2*)(C + (size_t)gr * N + gc) =
                make_float2(acc[mf][nf][0], acc[mf][nf][1]);
            *(float2*)(C + (size_t)(gr + 8) * N + gc) =
                make_float2(acc[mf][nf][2], acc[mf][nf][3]);
        }
    }
}

// ---------------------------------------------------------------------------
// Sliding-window attention, flash-style online softmax, fp32 (unchanged R1).
// ---------------------------------------------------------------------------
struct AttnSmem {
    float Qs[64][65];
    float Ks[64][65];
    float Vs[64][64];
    float Ss[64][68];
    float m_s[64], l_s[64], alpha_s[64];
};

__global__ __launch_bounds__(256) void attn_kernel(const float* __restrict__ qkv,
                                                   float* __restrict__ out) {
    extern __shared__ char smem_raw[];
    AttnSmem& sm = *reinterpret_cast<AttnSmem*>(smem_raw);

    const int qt = blockIdx.x;
    const int c  = blockIdx.y;
    const int h  = blockIdx.z;
    const int tid = threadIdx.x;
    const int tx = tid % 16, ty = tid / 16;

    const int q0 = qt * 64;
    const int qbase_row = c * WIN + q0;

    {
        const int q = tid >> 2;
        const float* src = qkv + (size_t)(qbase_row + q) * D3 + h * HDIM;
        #pragma unroll
        for (int i = 0; i < 4; i++) {
            int cd = (tid & 3) + i * 4;
            float4 v = *(const float4*)(src + cd * 4);
            sm.Qs[cd*4+0][q] = v.x; sm.Qs[cd*4+1][q] = v.y;
            sm.Qs[cd*4+2][q] = v.z; sm.Qs[cd*4+3][q] = v.w;
        }
    }
    if (tid < 64) { sm.m_s[tid] = -1e30f; sm.l_s[tid] = 0.f; }

    float o[4][4] = {};
    const int kb_start = (c == 0) ? (WIN / 64) : 0;
    const int kb_end = ((q0 + 63 + WIN) >> 6) + 1;

    for (int kb = kb_start; kb < kb_end; kb++) {
        const int j0 = kb * 64;
        __syncthreads();

        {
            const int j = tid >> 2;
            const int krow = c * WIN + j0 - WIN + j;
            const float* ksrc = qkv + (size_t)krow * D3 + DMODEL + h * HDIM;
            const float* vsrc = qkv + (size_t)krow * D3 + 2 * DMODEL + h * HDIM;
            #pragma unroll
            for (int i = 0; i < 4; i++) {
                int cd = (tid & 3) + i * 4;
                float4 kv = *(const float4*)(ksrc + cd * 4);
                sm.Ks[cd*4+0][j] = kv.x; sm.Ks[cd*4+1][j] = kv.y;
                sm.Ks[cd*4+2][j] = kv.z; sm.Ks[cd*4+3][j] = kv.w;
                float4 vv = *(const float4*)(vsrc + cd * 4);
                *(float4*)&sm.Vs[j][cd * 4] = vv;
            }
        }
        __syncthreads();

        float s[4][4] = {};
        #pragma unroll 8
        for (int d = 0; d < 64; d++) {
            float qr[4], kr[4];
            #pragma unroll
            for (int i = 0; i < 4; i++) qr[i] = sm.Qs[d][ty * 4 + i];
            #pragma unroll
            for (int j = 0; j < 4; j++) kr[j] = sm.Ks[d][tx * 4 + j];
            #pragma unroll
            for (int i = 0; i < 4; i++)
                #pragma unroll
                for (int j = 0; j < 4; j++) s[i][j] += qr[i] * kr[j];
        }
        #pragma unroll
        for (int i = 0; i < 4; i++)
            #pragma unroll
            for (int j = 0; j < 4; j++) {
                int qg = q0 + ty * 4 + i;
                int jg = j0 + tx * 4 + j;
                float val = (qg + WIN >= jg) ? s[i][j] * 0.125f : -1e30f;
                sm.Ss[tx * 4 + j][ty * 4 + i] = val;
            }
        __syncthreads();

        {
            const int q = tid >> 2;
            const int r = tid & 3;
            float mx = -1e30f;
            #pragma unroll
            for (int t = 0; t < 16; t++) mx = fmaxf(mx, sm.Ss[r * 16 + t][q]);
            mx = fmaxf(mx, __shfl_xor_sync(0xffffffffu, mx, 1));
            mx = fmaxf(mx, __shfl_xor_sync(0xffffffffu, mx, 2));
            const float m_old = sm.m_s[q];
            const float m_new = fmaxf(m_old, mx);
            float sum = 0.f;
            #pragma unroll
            for (int t = 0; t < 16; t++) {
                float p = __expf(sm.Ss[r * 16 + t][q] - m_new);
                sm.Ss[r * 16 + t][q] = p;
                sum += p;
            }
            sum += __shfl_xor_sync(0xffffffffu, sum, 1);
            sum += __shfl_xor_sync(0xffffffffu, sum, 2);
            if (r == 0) {
                float alpha = __expf(m_old - m_new);
                sm.m_s[q] = m_new;
                sm.l_s[q] = sm.l_s[q] * alpha + sum;
                sm.alpha_s[q] = alpha;
            }
        }
        __syncthreads();

        #pragma unroll
        for (int i = 0; i < 4; i++) {
            float a = sm.alpha_s[ty * 4 + i];
            #pragma unroll
            for (int j = 0; j < 4; j++) o[i][j] *= a;
        }
        #pragma unroll 4
        for (int k = 0; k < 64; k++) {
            float pr[4], vr[4];
            #pragma unroll
            for (int i = 0; i < 4; i++) pr[i] = sm.Ss[k][ty * 4 + i];
            #pragma unroll
            for (int j = 0; j < 4; j++) vr[j] = sm.Vs[k][tx * 4 + j];
            #pragma unroll
            for (int i = 0; i < 4; i++)
                #pragma unroll
                for (int j = 0; j < 4; j++) o[i][j] += pr[i] * vr[j];
        }
    }

    #pragma unroll
    for (int i = 0; i < 4; i++) {
        const int q = ty * 4 + i;
        const float inv = 1.f / sm.l_s[q];
        float4 v = make_float4(o[i][0] * inv, o[i][1] * inv,
                               o[i][2] * inv, o[i][3] * inv);
        *(float4*)(out + (size_t)(qbase_row + q) * DMODEL + h * HDIM + tx * 4) = v;
    }
}

// ---------------------------------------------------------------------------
extern "C" void kernel_launch(void* const* d_in, const int* in_sizes, int n_in,
                              void* d_out, int out_size) {
    const float* x      = (const float*)d_in[0];   // [4096,1024]
    const float* w_qkv  = (const float*)d_in[1];   // [1024,3072]
    const float* w_out  = (const float*)d_in[2];   // [1024,1024]
    float* out = (float*)d_out;                    // [4096,1024]

    float *qkv, *attn;
    cudaGetSymbolAddress((void**)&qkv, g_qkv);
    cudaGetSymbolAddress((void**)&attn, g_attn);

    const int gemm_smem = SM_TOTAL_U32 * 4;
    cudaFuncSetAttribute(gemm_3xtf32, cudaFuncAttributeMaxDynamicSharedMemorySize,
                         gemm_smem);
    cudaFuncSetAttribute(attn_kernel, cudaFuncAttributeMaxDynamicSharedMemorySize,
                         (int)sizeof(AttnSmem));

    // 1) qkv = x @ w_qkv   [4096,1024]x[1024,3072]
    gemm_3xtf32<<<dim3(D3 / 128, SEQ / 128), 256, gemm_smem>>>(x, w_qkv, qkv,
                                                               SEQ, D3, DMODEL);
    // 2) sliding-window attention
    attn_kernel<<<dim3(8, NCHUNK, NHEAD), 256, sizeof(AttnSmem)>>>(qkv, attn);
    // 3) out = attn @ w_out   [4096,1024]x[1024,1024]
    gemm_3xtf32<<<dim3(DMODEL / 128, SEQ / 128), 256, gemm_smem>>>(attn, w_out, out,
                                                                   SEQ, DMODEL, DMODEL);
}

// round 3
// speedup vs baseline: 1.4466x; 1.2017x over previous
#include <cuda_runtime.h>
#include <cuda_bf16.h>
#include <cstdint>

// Problem constants
#define SEQ    4096
#define DMODEL 1024
#define D3     3072
#define NHEAD  16
#define HDIM   64
#define WIN    512
#define NCHUNK 8

// Scratch (device globals: allocation-free per harness rules)
__device__ float g_qkv[SEQ * D3];        // 48 MB
__device__ float g_attn[SEQ * DMODEL];   // 16 MB

// ---------------------------------------------------------------------------
// tf32 helpers
// ---------------------------------------------------------------------------
__device__ __forceinline__ uint32_t f2tf32(float x) {
    uint32_t r;
    asm("cvt.rna.tf32.f32 %0, %1;" : "=r"(r) : "f"(x));
    return r;
}
__device__ __forceinline__ void split_tf32(float x, uint32_t& hi, uint32_t& lo) {
    hi = f2tf32(x);
    float l = x - __uint_as_float(hi);   // exact (Dekker split)
    lo = f2tf32(l);
}

#define MMA_TF32(d, a0, a1, a2, a3, b0, b1)                                    \
    asm volatile(                                                              \
        "mma.sync.aligned.m16n8k8.row.col.f32.tf32.tf32.f32 "                  \
        "{%0,%1,%2,%3}, {%4,%5,%6,%7}, {%8,%9}, {%0,%1,%2,%3};"                \
        : "+f"((d)[0]), "+f"((d)[1]), "+f"((d)[2]), "+f"((d)[3])               \
        : "r"(a0), "r"(a1), "r"(a2), "r"(a3), "r"(b0), "r"(b1))

#define LDSM_X4(r0, r1, r2, r3, addr)                                          \
    asm volatile("ldmatrix.sync.aligned.m8n8.x4.shared.b16 {%0,%1,%2,%3}, [%4];" \
        : "=r"(r0), "=r"(r1), "=r"(r2), "=r"(r3) : "r"(addr))

// ---------------------------------------------------------------------------
// 3xTF32 GEMM, 128x128 CTA tile, BK=32, 256 threads (8 warps: 2m x 4n).
// Double-buffered smem + register prefetch of next global tile.
// ---------------------------------------------------------------------------
#define SM_AH 0
#define SM_AL 4096
#define SM_BH 8192
#define SM_BL (8192 + 4224)
#define SM_STAGE_U32 (8192 + 2 * 4224)        // 16640 u32 per stage
#define SM_TOTAL_U32 (2 * SM_STAGE_U32)       // 33280 u32 = 133120 B

__global__ __launch_bounds__(256) void gemm_3xtf32(const float* __restrict__ A,
                                                   const float* __restrict__ B,
                                                   float* __restrict__ C,
                                                   int M, int N, int K) {
    extern __shared__ uint32_t sm[];

    const int tid  = threadIdx.x;
    const int lane = tid & 31;
    const int warp = tid >> 5;
    const int warp_m = warp >> 2;        // 0..1
    const int warp_n = warp & 3;         // 0..3

    const int m0 = blockIdx.y * 128;
    const int n0 = blockIdx.x * 128;

    const int a_m_base = tid >> 3;       // 0..31
    const int a_kc     = tid & 7;        // 16B chunk within 32-float row
    const int b_n4 = tid & 31;
    const int b_k  = tid >> 5;           // 0..7

    const int lm_row  = (lane & 7) + ((lane >> 3) & 1) * 8;  // 0..15
    const int lm_csel = lane >> 4;                            // 0/1

    const int bf_n = lane >> 2;          // 0..7
    const int bf_k = lane & 3;           // 0..3

    float acc[4][4][4] = {};

    const uint32_t sm_base = (uint32_t)__cvta_generic_to_shared(sm);
    const int a_sw = (a_kc ^ (a_m_base & 7)) << 2;   // swizzled chunk offset (row-invariant under +32)

    // ---- prologue: load tile 0, split, store stage 0 ----
    {
        uint32_t* Ah = sm + SM_AH;
        uint32_t* Al = sm + SM_AL;
        uint32_t* Bh = sm + SM_BH;
        uint32_t* Bl = sm + SM_BL;
        #pragma unroll
        for (int r = 0; r < 4; r++) {
            const int m = a_m_base + 32 * r;
            const float4 v = *(const float4*)(A + (size_t)(m0 + m) * K + a_kc * 4);
            uint4 h, l;
            split_tf32(v.x, h.x, l.x); split_tf32(v.y, h.y, l.y);
            split_tf32(v.z, h.z, l.z); split_tf32(v.w, h.w, l.w);
            const int off = m * 32 + a_sw;
            *(uint4*)&Ah[off] = h; *(uint4*)&Al[off] = l;
        }
        #pragma unroll
        for (int r = 0; r < 4; r++) {
            const int k = b_k + 8 * r;
            const float4 v = *(const float4*)(B + (size_t)k * N + n0 + b_n4 * 4);
            uint4 h, l;
            split_tf32(v.x, h.x, l.x); split_tf32(v.y, h.y, l.y);
            split_tf32(v.z, h.z, l.z); split_tf32(v.w, h.w, l.w);
            const int off = k * 132 + b_n4 * 4;
            *(uint4*)&Bh[off] = h; *(uint4*)&Bl[off] = l;
        }
    }
    __syncthreads();

    int stage = 0;
    for (int k0 = 0; k0 < K; k0 += 32) {
        // ---- prefetch next tile into registers ----
        float4 pa[4], pb[4];
        const bool has_next = (k0 + 32) < K;
        if (has_next) {
            #pragma unroll
            for (int r = 0; r < 4; r++) {
                const int m = a_m_base + 32 * r;
                pa[r] = *(const float4*)(A + (size_t)(m0 + m) * K + (k0 + 32) + a_kc * 4);
            }
            #pragma unroll
            for (int r = 0; r < 4; r++) {
                const int k = b_k + 8 * r;
                pb[r] = *(const float4*)(B + (size_t)(k0 + 32 + k) * N + n0 + b_n4 * 4);
            }
        }

        // ---- compute current stage ----
        const uint32_t ah_base = sm_base + 4u * (stage * SM_STAGE_U32 + SM_AH);
        const uint32_t al_base = sm_base + 4u * (stage * SM_STAGE_U32 + SM_AL);
        const uint32_t* Bh = sm + stage * SM_STAGE_U32 + SM_BH;
        const uint32_t* Bl = sm + stage * SM_STAGE_U32 + SM_BL;

        #pragma unroll
        for (int k8 = 0; k8 < 4; k8++) {
            const int c0 = k8 * 2;
            uint32_t aH[4][4], aL[4][4];
            #pragma unroll
            for (int mf = 0; mf < 4; mf++) {
                const int m = warp_m * 64 + mf * 16 + lm_row;
                const uint32_t foff =
                    4u * (m * 32 + (((c0 + lm_csel) ^ (m & 7)) << 2));
                LDSM_X4(aH[mf][0], aH[mf][1], aH[mf][2], aH[mf][3], ah_base + foff);
                LDSM_X4(aL[mf][0], aL[mf][1], aL[mf][2], aL[mf][3], al_base + foff);
            }
            const int kk = k8 * 8;
            #pragma unroll
            for (int nf = 0; nf < 4; nf++) {
                const int n = warp_n * 32 + nf * 8 + bf_n;
                const int r0 = (kk + bf_k) * 132 + n;
                const int r1 = r0 + 4 * 132;
                const uint32_t bh0 = Bh[r0], bh1 = Bh[r1];
                const uint32_t bl0 = Bl[r0], bl1 = Bl[r1];
                #pragma unroll
                for (int mf = 0; mf < 4; mf++) {
                    MMA_TF32(acc[mf][nf], aH[mf][0], aH[mf][1], aH[mf][2], aH[mf][3], bh0, bh1);
                    MMA_TF32(acc[mf][nf], aH[mf][0], aH[mf][1], aH[mf][2], aH[mf][3], bl0, bl1);
                    MMA_TF32(acc[mf][nf], aL[mf][0], aL[mf][1], aL[mf][2], aL[mf][3], bh0, bh1);
                }
            }
        }

        // ---- store prefetched tile to other stage ----
        if (has_next) {
            stage ^= 1;
            uint32_t* Ah2 = sm + stage * SM_STAGE_U32 + SM_AH;
            uint32_t* Al2 = sm + stage * SM_STAGE_U32 + SM_AL;
            uint32_t* Bh2 = sm + stage * SM_STAGE_U32 + SM_BH;
            uint32_t* Bl2 = sm + stage * SM_STAGE_U32 + SM_BL;
            #pragma unroll
            for (int r = 0; r < 4; r++) {
                const int m = a_m_base + 32 * r;
                uint4 h, l;
                split_tf32(pa[r].x, h.x, l.x); split_tf32(pa[r].y, h.y, l.y);
                split_tf32(pa[r].z, h.z, l.z); split_tf32(pa[r].w, h.w, l.w);
                const int off = m * 32 + a_sw;
                *(uint4*)&Ah2[off] = h; *(uint4*)&Al2[off] = l;
            }
            #pragma unroll
            for (int r = 0; r < 4; r++) {
                const int k = b_k + 8 * r;
                uint4 h, l;
                split_tf32(pb[r].x, h.x, l.x); split_tf32(pb[r].y, h.y, l.y);
                split_tf32(pb[r].z, h.z, l.z); split_tf32(pb[r].w, h.w, l.w);
                const int off = k * 132 + b_n4 * 4;
                *(uint4*)&Bh2[off] = h; *(uint4*)&Bl2[off] = l;
            }
            __syncthreads();
        }
    }

    // ---- epilogue ----
    const int row_in = lane >> 2;
    const int col_in = 2 * (lane & 3);
    #pragma unroll
    for (int mf = 0; mf < 4; mf++) {
        const int gr = m0 + warp_m * 64 + mf * 16 + row_in;
        #pragma unroll
        for (int nf = 0; nf < 4; nf++) {
            const int gc = n0 + warp_n * 32 + nf * 8 + col_in;
            *(float2*)(C + (size_t)gr * N + gc) =
                make_float2(acc[mf][nf][0], acc[mf][nf][1]);
            *(float2*)(C + (size_t)(gr + 8) * N + gc) =
                make_float2(acc[mf][nf][2], acc[mf][nf][3]);
        }
    }
}

// ---------------------------------------------------------------------------
// Sliding-window attention with 3xTF32 tensor-core MMAs.
// Block = (64-query tile qt, chunk c, head h), 256 threads = 8 warps (2m x 4n).
// QK^T: Q hi/lo smem planes via ldmatrix; K raw in smem [d][j], split at read.
// Softmax in smem (R1 scheme, [q][j] layout), P split into Ph/Pl planes.
// PV: Ph/Pl via ldmatrix; V raw in smem [j][d], split at read.
// ---------------------------------------------------------------------------
struct AttnSmem2 {
    float Qh[64][68];
    float Ql[64][68];
    float Ks[64][68];   // [d][j] raw
    float Vs[64][68];   // [j][d] raw
    float Ss[64][68];   // [q][j] scores
    float Ph[64][68];   // [q][j] split prob hi
    float Pl[64][68];   // [q][j] split prob lo
    float m_s[64], l_s[64], alpha_s[64];
};

__global__ __launch_bounds__(256) void attn_mma(const float* __restrict__ qkv,
                                                float* __restrict__ out) {
    extern __shared__ char smem_raw[];
    AttnSmem2& sm = *reinterpret_cast<AttnSmem2*>(smem_raw);

    const int qt = blockIdx.x;   // 0..7
    const int c  = blockIdx.y;   // 0..7
    const int h  = blockIdx.z;   // 0..15
    const int tid  = threadIdx.x;
    const int lane = tid & 31;
    const int warp = tid >> 5;
    const int warp_m = warp >> 2;   // 0..1 (32 q rows each)
    const int warp_n = warp & 3;    // 0..3 (16 cols each)

    const int q0 = qt * 64;
    const int qrow0 = c * WIN + q0;

    const int lm_row  = (lane & 7) + ((lane >> 3) & 1) * 8;
    const int lm_csel = lane >> 4;
    const int bf_n = lane >> 2;     // 0..7
    const int bf_k = lane & 3;      // 0..3

    const uint32_t qh_base = (uint32_t)__cvta_generic_to_shared(&sm.Qh[0][0]);
    const uint32_t ql_base = (uint32_t)__cvta_generic_to_shared(&sm.Ql[0][0]);
    const uint32_t ph_base = (uint32_t)__cvta_generic_to_shared(&sm.Ph[0][0]);
    const uint32_t pl_base = (uint32_t)__cvta_generic_to_shared(&sm.Pl[0][0]);

    // ---- load Q tile, split into Qh/Ql ----
    {
        const int q = tid >> 2;
        const float* src = qkv + (size_t)(qrow0 + q) * D3 + h * HDIM;
        #pragma unroll
        for (int i = 0; i < 4; i++) {
            const int cd = (tid & 3) + i * 4;
            const float4 v = *(const float4*)(src + cd * 4);
            uint4 hh, ll;
            split_tf32(v.x, hh.x, ll.x); split_tf32(v.y, hh.y, ll.y);
            split_tf32(v.z, hh.z, ll.z); split_tf32(v.w, hh.w, ll.w);
            *(uint4*)&sm.Qh[q][cd * 4] = hh;
            *(uint4*)&sm.Ql[q][cd * 4] = ll;
        }
    }
    if (tid < 64) { sm.m_s[tid] = -1e30f; sm.l_s[tid] = 0.f; }

    float o[2][2][4] = {};
    const int kb_start = (c == 0) ? (WIN / 64) : 0;
    const int kb_end = ((q0 + 63 + WIN) >> 6) + 1;   // exclusive, <= 16

    for (int kb = kb_start; kb < kb_end; kb++) {
        const int j0 = kb * 64;
        __syncthreads();   // prev PV done with Vs/Ph/Pl; Q/stats ready on iter 1

        // ---- load K (transposed [d][j]) and V ([j][d]) raw ----
        {
            const int j = tid >> 2;
            const int krow = c * WIN + j0 - WIN + j;
            const float* ksrc = qkv + (size_t)krow * D3 + DMODEL + h * HDIM;
            const float* vsrc = qkv + (size_t)krow * D3 + 2 * DMODEL + h * HDIM;
            #pragma unroll
            for (int i = 0; i < 4; i++) {
                const int cd = (tid & 3) + i * 4;
                const float4 kv = *(const float4*)(ksrc + cd * 4);
                sm.Ks[cd*4+0][j] = kv.x; sm.Ks[cd*4+1][j] = kv.y;
                sm.Ks[cd*4+2][j] = kv.z; sm.Ks[cd*4+3][j] = kv.w;
                const float4 vv = *(const float4*)(vsrc + cd * 4);
                *(float4*)&sm.Vs[j][cd * 4] = vv;
            }
        }
        __syncthreads();

        // ---- S = Q K^T (64x64x64), 3xtf32 ----
        float s[2][2][4] = {};
        #pragma unroll
        for (int k8 = 0; k8 < 8; k8++) {
            uint32_t aH[2][4], aL[2][4];
            #pragma unroll
            for (int mf = 0; mf < 2; mf++) {
                const int qrow = warp_m * 32 + mf * 16 + lm_row;
                const uint32_t foff = 4u * (qrow * 68 + (k8 * 2 + lm_csel) * 4);
                LDSM_X4(aH[mf][0], aH[mf][1], aH[mf][2], aH[mf][3], qh_base + foff);
                LDSM_X4(aL[mf][0], aL[mf][1], aL[mf][2], aL[mf][3], ql_base + foff);
            }
            const int kk = k8 * 8;
            #pragma unroll
            for (int nf = 0; nf < 2; nf++) {
                const int j = warp_n * 16 + nf * 8 + bf_n;
                uint32_t bh0, bl0, bh1, bl1;
                split_tf32(sm.Ks[kk + bf_k][j], bh0, bl0);
                split_tf32(sm.Ks[kk + 4 + bf_k][j], bh1, bl1);
                #pragma unroll
                for (int mf = 0; mf < 2; mf++) {
                    MMA_TF32(s[mf][nf], aH[mf][0], aH[mf][1], aH[mf][2], aH[mf][3], bh0, bh1);
                    MMA_TF32(s[mf][nf], aH[mf][0], aH[mf][1], aH[mf][2], aH[mf][3], bl0, bl1);
                    MMA_TF32(s[mf][nf], aL[mf][0], aL[mf][1], aL[mf][2], aL[mf][3], bh0, bh1);
                }
            }
        }

        // ---- mask + scale, write scores to Ss[q][j] ----
        #pragma unroll
        for (int mf = 0; mf < 2; mf++) {
            const int r0 = warp_m * 32 + mf * 16 + (lane >> 2);
            #pragma unroll
            for (int nf = 0; nf < 2; nf++) {
                const int cb = warp_n * 16 + nf * 8 + 2 * (lane & 3);
                const int jg0 = j0 + cb;
                const float sc = 0.125f;
                sm.Ss[r0][cb]       = (q0 + r0 + WIN >= jg0)     ? s[mf][nf][0] * sc : -1e30f;
                sm.Ss[r0][cb + 1]   = (q0 + r0 + WIN >= jg0 + 1) ? s[mf][nf][1] * sc : -1e30f;
                sm.Ss[r0 + 8][cb]     = (q0 + r0 + 8 + WIN >= jg0)     ? s[mf][nf][2] * sc : -1e30f;
                sm.Ss[r0 + 8][cb + 1] = (q0 + r0 + 8 + WIN >= jg0 + 1) ? s[mf][nf][3] * sc : -1e30f;
            }
        }
        __syncthreads();

        // ---- online softmax (4 threads per query row), write Ph/Pl ----
        {
            const int q = tid >> 2;
            const int r = tid & 3;
            float mx = -1e30f;
            #pragma unroll
            for (int t = 0; t < 16; t++) mx = fmaxf(mx, sm.Ss[q][r * 16 + t]);
            mx = fmaxf(mx, __shfl_xor_sync(0xffffffffu, mx, 1));
            mx = fmaxf(mx, __shfl_xor_sync(0xffffffffu, mx, 2));
            const float m_old = sm.m_s[q];
            const float m_new = fmaxf(m_old, mx);
            float sum = 0.f;
            #pragma unroll
            for (int t = 0; t < 16; t++) {
                const float p = __expf(sm.Ss[q][r * 16 + t] - m_new);
                sum += p;
                uint32_t ph, pl;
                split_tf32(p, ph, pl);
                sm.Ph[q][r * 16 + t] = __uint_as_float(ph);
                sm.Pl[q][r * 16 + t] = __uint_as_float(pl);
            }
            sum += __shfl_xor_sync(0xffffffffu, sum, 1);
            sum += __shfl_xor_sync(0xffffffffu, sum, 2);
            if (r == 0) {
                const float alpha = __expf(m_old - m_new);
                sm.m_s[q] = m_new;
                sm.l_s[q] = sm.l_s[q] * alpha + sum;
                sm.alpha_s[q] = alpha;
            }
        }
        __syncthreads();

        // ---- O = O*alpha + P V (64x64x64), 3xtf32 ----
        #pragma unroll
        for (int mf = 0; mf < 2; mf++) {
            const int r0 = warp_m * 32 + mf * 16 + (lane >> 2);
            const float a0 = sm.alpha_s[r0];
            const float a1 = sm.alpha_s[r0 + 8];
            #pragma unroll
            for (int nf = 0; nf < 2; nf++) {
                o[mf][nf][0] *= a0; o[mf][nf][1] *= a0;
                o[mf][nf][2] *= a1; o[mf][nf][3] *= a1;
            }
        }
        #pragma unroll
        for (int k8 = 0; k8 < 8; k8++) {
            uint32_t aH[2][4], aL[2][4];
            #pragma unroll
            for (int mf = 0; mf < 2; mf++) {
                const int qrow = warp_m * 32 + mf * 16 + lm_row;
                const uint32_t foff = 4u * (qrow * 68 + (k8 * 2 + lm_csel) * 4);
                LDSM_X4(aH[mf][0], aH[mf][1], aH[mf][2], aH[mf][3], ph_base + foff);
                LDSM_X4(aL[mf][0], aL[mf][1], aL[mf][2], aL[mf][3], pl_base + foff);
            }
            const int kk = k8 * 8;
            #pragma unroll
            for (int nf = 0; nf < 2; nf++) {
                const int d = warp_n * 16 + nf * 8 + bf_n;
                uint32_t bh0, bl0, bh1, bl1;
                split_tf32(sm.Vs[kk + bf_k][d], bh0, bl0);
                split_tf32(sm.Vs[kk + 4 + bf_k][d], bh1, bl1);
                #pragma unroll
                for (int mf = 0; mf < 2; mf++) {
                    MMA_TF32(o[mf][nf], aH[mf][0], aH[mf][1], aH[mf][2], aH[mf][3], bh0, bh1);
                    MMA_TF32(o[mf][nf], aH[mf][0], aH[mf][1], aH[mf][2], aH[mf][3], bl0, bl1);
                    MMA_TF32(o[mf][nf], aL[mf][0], aL[mf][1], aL[mf][2], aL[mf][3], bh0, bh1);
                }
            }
        }
    }

    // ---- finalize: divide by l, write out ----
    #pragma unroll
    for (int mf = 0; mf < 2; mf++) {
        const int r0 = warp_m * 32 + mf * 16 + (lane >> 2);
        const float inv0 = 1.f / sm.l_s[r0];
        const float inv1 = 1.f / sm.l_s[r0 + 8];
        #pragma unroll
        for (int nf = 0; nf < 2; nf++) {
            const int col = h * HDIM + warp_n * 16 + nf * 8 + 2 * (lane & 3);
            *(float2*)(out + (size_t)(qrow0 + r0) * DMODEL + col) =
                make_float2(o[mf][nf][0] * inv0, o[mf][nf][1] * inv0);
            *(float2*)(out + (size_t)(qrow0 + r0 + 8) * DMODEL + col) =
                make_float2(o[mf][nf][2] * inv1, o[mf][nf][3] * inv1);
        }
    }
}

// ---------------------------------------------------------------------------
extern "C" void kernel_launch(void* const* d_in, const int* in_sizes, int n_in,
                              void* d_out, int out_size) {
    const float* x      = (const float*)d_in[0];   // [4096,1024]
    const float* w_qkv  = (const float*)d_in[1];   // [1024,3072]
    const float* w_out  = (const float*)d_in[2];   // [1024,1024]
    float* out = (float*)d_out;                    // [4096,1024]

    float *qkv, *attn;
    cudaGetSymbolAddress((void**)&qkv, g_qkv);
    cudaGetSymbolAddress((void**)&attn, g_attn);

    const int gemm_smem = SM_TOTAL_U32 * 4;
    cudaFuncSetAttribute(gemm_3xtf32, cudaFuncAttributeMaxDynamicSharedMemorySize,
                         gemm_smem);
    cudaFuncSetAttribute(attn_mma, cudaFuncAttributeMaxDynamicSharedMemorySize,
                         (int)sizeof(AttnSmem2));

    // 1) qkv = x @ w_qkv   [4096,1024]x[1024,3072]
    gemm_3xtf32<<<dim3(D3 / 128, SEQ / 128), 256, gemm_smem>>>(x, w_qkv, qkv,
                                                               SEQ, D3, DMODEL);
    // 2) sliding-window attention (tensor-core)
    attn_mma<<<dim3(8, NCHUNK, NHEAD), 256, sizeof(AttnSmem2)>>>(qkv, attn);
    // 3) out = attn @ w_out   [4096,1024]x[1024,1024]
    gemm_3xtf32<<<dim3(DMODEL / 128, SEQ / 128), 256, gemm_smem>>>(attn, w_out, out,
                                                                   SEQ, DMODEL, DMODEL);
}

// round 5
// speedup vs baseline: 1.5789x; 1.0915x over previous
#include <cuda_runtime.h>
#include <cuda_bf16.h>
#include <cstdint>

// Problem constants
#define SEQ    4096
#define DMODEL 1024
#define D3     3072
#define NHEAD  16
#define HDIM   64
#define WIN    512
#define NCHUNK 8

// Scratch (device globals: allocation-free per harness rules)
__device__ float g_qkv[SEQ * D3];        // 48 MB
__device__ float g_attn[SEQ * DMODEL];   // 16 MB

// ---------------------------------------------------------------------------
// tf32 helpers
// ---------------------------------------------------------------------------
__device__ __forceinline__ uint32_t f2tf32(float x) {
    uint32_t r;
    asm("cvt.rna.tf32.f32 %0, %1;" : "=r"(r) : "f"(x));
    return r;
}
__device__ __forceinline__ void split_tf32(float x, uint32_t& hi, uint32_t& lo) {
    hi = f2tf32(x);
    float l = x - __uint_as_float(hi);   // exact (Dekker split)
    lo = f2tf32(l);
}

#define MMA_TF32(d, a0, a1, a2, a3, b0, b1)                                    \
    asm volatile(                                                              \
        "mma.sync.aligned.m16n8k8.row.col.f32.tf32.tf32.f32 "                  \
        "{%0,%1,%2,%3}, {%4,%5,%6,%7}, {%8,%9}, {%0,%1,%2,%3};"                \
        : "+f"((d)[0]), "+f"((d)[1]), "+f"((d)[2]), "+f"((d)[3])               \
        : "r"(a0), "r"(a1), "r"(a2), "r"(a3), "r"(b0), "r"(b1))

#define LDSM_X4(r0, r1, r2, r3, addr)                                          \
    asm volatile("ldmatrix.sync.aligned.m8n8.x4.shared.b16 {%0,%1,%2,%3}, [%4];" \
        : "=r"(r0), "=r"(r1), "=r"(r2), "=r"(r3) : "r"(addr))

// ---------------------------------------------------------------------------
// 3xTF32 GEMM, 128x128 CTA tile, BK=32, 256 threads (8 warps: 2m x 4n).
// Single-stage smem (66.5 KB) so TWO CTAs fit per SM: cross-CTA overlap hides
// the load+split phase instead of an intra-CTA double buffer.
// ---------------------------------------------------------------------------
#define SM_AH 0
#define SM_AL 4096
#define SM_BH 8192
#define SM_BL (8192 + 4224)
#define SM_TOTAL_U32 (8192 + 2 * 4224)   // 16640 u32 = 66560 B

__global__ __launch_bounds__(256, 2) void gemm_3xtf32(const float* __restrict__ A,
                                                      const float* __restrict__ B,
                                                      float* __restrict__ C,
                                                      int M, int N, int K) {
    extern __shared__ uint32_t sm[];
    uint32_t* __restrict__ Ah = sm + SM_AH;
    uint32_t* __restrict__ Al = sm + SM_AL;
    uint32_t* __restrict__ Bh = sm + SM_BH;
    uint32_t* __restrict__ Bl = sm + SM_BL;

    const int tid  = threadIdx.x;
    const int lane = tid & 31;
    const int warp = tid >> 5;
    const int warp_m = warp >> 2;        // 0..1
    const int warp_n = warp & 3;         // 0..3

    const int m0 = blockIdx.y * 128;
    const int n0 = blockIdx.x * 128;

    const int a_m_base = tid >> 3;       // 0..31
    const int a_kc     = tid & 7;        // 16B chunk within 32-float row
    const int b_n4 = tid & 31;
    const int b_k  = tid >> 5;           // 0..7

    const int lm_row  = (lane & 7) + ((lane >> 3) & 1) * 8;  // 0..15
    const int lm_csel = lane >> 4;                            // 0/1

    const int bf_n = lane >> 2;          // 0..7
    const int bf_k = lane & 3;           // 0..3

    float acc[4][4][4] = {};

    const uint32_t ah_base = (uint32_t)__cvta_generic_to_shared(Ah);
    const uint32_t al_base = (uint32_t)__cvta_generic_to_shared(Al);
    const int a_sw = (a_kc ^ (a_m_base & 7)) << 2;

    for (int k0 = 0; k0 < K; k0 += 32) {
        if (k0) __syncthreads();   // previous compute done before overwrite

        // ---- load + split A tile (128 x 32) ----
        #pragma unroll
        for (int r = 0; r < 4; r++) {
            const int m = a_m_base + 32 * r;
            const float4 v = *(const float4*)(A + (size_t)(m0 + m) * K + k0 + a_kc * 4);
            uint4 h, l;
            split_tf32(v.x, h.x, l.x); split_tf32(v.y, h.y, l.y);
            split_tf32(v.z, h.z, l.z); split_tf32(v.w, h.w, l.w);
            const int off = m * 32 + a_sw;
            *(uint4*)&Ah[off] = h; *(uint4*)&Al[off] = l;
        }
        // ---- load + split B tile (32 x 128) ----
        #pragma unroll
        for (int r = 0; r < 4; r++) {
            const int k = b_k + 8 * r;
            const float4 v = *(const float4*)(B + (size_t)(k0 + k) * N + n0 + b_n4 * 4);
            uint4 h, l;
            split_tf32(v.x, h.x, l.x); split_tf32(v.y, h.y, l.y);
            split_tf32(v.z, h.z, l.z); split_tf32(v.w, h.w, l.w);
            const int off = k * 132 + b_n4 * 4;
            *(uint4*)&Bh[off] = h; *(uint4*)&Bl[off] = l;
        }
        __syncthreads();

        // ---- compute: 4 k8-steps ----
        #pragma unroll
        for (int k8 = 0; k8 < 4; k8++) {
            const int c0 = k8 * 2;
            uint32_t aH[4][4], aL[4][4];
            #pragma unroll
            for (int mf = 0; mf < 4; mf++) {
                const int m = warp_m * 64 + mf * 16 + lm_row;
                const uint32_t foff =
                    4u * (m * 32 + (((c0 + lm_csel) ^ (m & 7)) << 2));
                LDSM_X4(aH[mf][0], aH[mf][1], aH[mf][2], aH[mf][3], ah_base + foff);
                LDSM_X4(aL[mf][0], aL[mf][1], aL[mf][2], aL[mf][3], al_base + foff);
            }
            const int kk = k8 * 8;
            #pragma unroll
            for (int nf = 0; nf < 4; nf++) {
                const int n = warp_n * 32 + nf * 8 + bf_n;
                const int r0 = (kk + bf_k) * 132 + n;
                const int r1 = r0 + 4 * 132;
                const uint32_t bh0 = Bh[r0], bh1 = Bh[r1];
                const uint32_t bl0 = Bl[r0], bl1 = Bl[r1];
                #pragma unroll
                for (int mf = 0; mf < 4; mf++) {
                    MMA_TF32(acc[mf][nf], aH[mf][0], aH[mf][1], aH[mf][2], aH[mf][3], bh0, bh1);
                    MMA_TF32(acc[mf][nf], aH[mf][0], aH[mf][1], aH[mf][2], aH[mf][3], bl0, bl1);
                    MMA_TF32(acc[mf][nf], aL[mf][0], aL[mf][1], aL[mf][2], aL[mf][3], bh0, bh1);
                }
            }
        }
    }

    // ---- epilogue ----
    const int row_in = lane >> 2;
    const int col_in = 2 * (lane & 3);
    #pragma unroll
    for (int mf = 0; mf < 4; mf++) {
        const int gr = m0 + warp_m * 64 + mf * 16 + row_in;
        #pragma unroll
        for (int nf = 0; nf < 4; nf++) {
            const int gc = n0 + warp_n * 32 + nf * 8 + col_in;
            *(float2*)(C + (size_t)gr * N + gc) =
                make_float2(acc[mf][nf][0], acc[mf][nf][1]);
            *(float2*)(C + (size_t)(gr + 8) * N + gc) =
                make_float2(acc[mf][nf][2], acc[mf][nf][3]);
        }
    }
}

// ---------------------------------------------------------------------------
// Sliding-window attention with 3xTF32 tensor-core MMAs.
// Smem trimmed to 6 planes (score plane aliased with Ph) -> 2 CTAs/SM.
// ---------------------------------------------------------------------------
struct AttnSmem2 {
    float Qh[64][68];
    float Ql[64][68];
    float Ks[64][68];   // [d][j] raw
    float Vs[64][68];   // [j][d] raw
    float Ps[64][68];   // [q][j]: scores, then overwritten with split-prob hi
    float Pl[64][68];   // [q][j]: split-prob lo
    float m_s[64], l_s[64], alpha_s[64];
};

__global__ __launch_bounds__(256, 2) void attn_mma(const float* __restrict__ qkv,
                                                   float* __restrict__ out) {
    extern __shared__ char smem_raw[];
    AttnSmem2& sm = *reinterpret_cast<AttnSmem2*>(smem_raw);

    const int qt = blockIdx.x;
    const int c  = blockIdx.y;
    const int h  = blockIdx.z;
    const int tid  = threadIdx.x;
    const int lane = tid & 31;
    const int warp = tid >> 5;
    const int warp_m = warp >> 2;
    const int warp_n = warp & 3;

    const int q0 = qt * 64;
    const int qrow0 = c * WIN + q0;

    const int lm_row  = (lane & 7) + ((lane >> 3) & 1) * 8;
    const int lm_csel = lane >> 4;
    const int bf_n = lane >> 2;
    const int bf_k = lane & 3;

    const uint32_t qh_base = (uint32_t)__cvta_generic_to_shared(&sm.Qh[0][0]);
    const uint32_t ql_base = (uint32_t)__cvta_generic_to_shared(&sm.Ql[0][0]);
    const uint32_t ps_base = (uint32_t)__cvta_generic_to_shared(&sm.Ps[0][0]);
    const uint32_t pl_base = (uint32_t)__cvta_generic_to_shared(&sm.Pl[0][0]);

    {
        const int q = tid >> 2;
        const float* src = qkv + (size_t)(qrow0 + q) * D3 + h * HDIM;
        #pragma unroll
        for (int i = 0; i < 4; i++) {
            const int cd = (tid & 3) + i * 4;
            const float4 v = *(const float4*)(src + cd * 4);
            uint4 hh, ll;
            split_tf32(v.x, hh.x, ll.x); split_tf32(v.y, hh.y, ll.y);
            split_tf32(v.z, hh.z, ll.z); split_tf32(v.w, hh.w, ll.w);
            *(uint4*)&sm.Qh[q][cd * 4] = hh;
            *(uint4*)&sm.Ql[q][cd * 4] = ll;
        }
    }
    if (tid < 64) { sm.m_s[tid] = -1e30f; sm.l_s[tid] = 0.f; }

    float o[2][2][4] = {};
    const int kb_start = (c == 0) ? (WIN / 64) : 0;
    const int kb_end = ((q0 + 63 + WIN) >> 6) + 1;

    for (int kb = kb_start; kb < kb_end; kb++) {
        const int j0 = kb * 64;
        __syncthreads();

        {
            const int j = tid >> 2;
            const int krow = c * WIN + j0 - WIN + j;
            const float* ksrc = qkv + (size_t)krow * D3 + DMODEL + h * HDIM;
            const float* vsrc = qkv + (size_t)krow * D3 + 2 * DMODEL + h * HDIM;
            #pragma unroll
            for (int i = 0; i < 4; i++) {
                const int cd = (tid & 3) + i * 4;
                const float4 kv = *(const float4*)(ksrc + cd * 4);
                sm.Ks[cd*4+0][j] = kv.x; sm.Ks[cd*4+1][j] = kv.y;
                sm.Ks[cd*4+2][j] = kv.z; sm.Ks[cd*4+3][j] = kv.w;
                const float4 vv = *(const float4*)(vsrc + cd * 4);
                *(float4*)&sm.Vs[j][cd * 4] = vv;
            }
        }
        __syncthreads();

        // ---- S = Q K^T (64x64x64), 3xtf32 ----
        float s[2][2][4] = {};
        #pragma unroll
        for (int k8 = 0; k8 < 8; k8++) {
            uint32_t aH[2][4], aL[2][4];
            #pragma unroll
            for (int mf = 0; mf < 2; mf++) {
                const int qrow = warp_m * 32 + mf * 16 + lm_row;
                const uint32_t foff = 4u * (qrow * 68 + (k8 * 2 + lm_csel) * 4);
                LDSM_X4(aH[mf][0], aH[mf][1], aH[mf][2], aH[mf][3], qh_base + foff);
                LDSM_X4(aL[mf][0], aL[mf][1], aL[mf][2], aL[mf][3], ql_base + foff);
            }
            const int kk = k8 * 8;
            #pragma unroll
            for (int nf = 0; nf < 2; nf++) {
                const int j = warp_n * 16 + nf * 8 + bf_n;
                uint32_t bh0, bl0, bh1, bl1;
                split_tf32(sm.Ks[kk + bf_k][j], bh0, bl0);
                split_tf32(sm.Ks[kk + 4 + bf_k][j], bh1, bl1);
                #pragma unroll
                for (int mf = 0; mf < 2; mf++) {
                    MMA_TF32(s[mf][nf], aH[mf][0], aH[mf][1], aH[mf][2], aH[mf][3], bh0, bh1);
                    MMA_TF32(s[mf][nf], aH[mf][0], aH[mf][1], aH[mf][2], aH[mf][3], bl0, bl1);
                    MMA_TF32(s[mf][nf], aL[mf][0], aL[mf][1], aL[mf][2], aL[mf][3], bh0, bh1);
                }
            }
        }

        // ---- mask + scale, write scores to Ps[q][j] ----
        #pragma unroll
        for (int mf = 0; mf < 2; mf++) {
            const int r0 = warp_m * 32 + mf * 16 + (lane >> 2);
            #pragma unroll
            for (int nf = 0; nf < 2; nf++) {
                const int cb = warp_n * 16 + nf * 8 + 2 * (lane & 3);
                const int jg0 = j0 + cb;
                const float sc = 0.125f;
                sm.Ps[r0][cb]       = (q0 + r0 + WIN >= jg0)     ? s[mf][nf][0] * sc : -1e30f;
                sm.Ps[r0][cb + 1]   = (q0 + r0 + WIN >= jg0 + 1) ? s[mf][nf][1] * sc : -1e30f;
                sm.Ps[r0 + 8][cb]     = (q0 + r0 + 8 + WIN >= jg0)     ? s[mf][nf][2] * sc : -1e30f;
                sm.Ps[r0 + 8][cb + 1] = (q0 + r0 + 8 + WIN >= jg0 + 1) ? s[mf][nf][3] * sc : -1e30f;
            }
        }
        __syncthreads();

        // ---- online softmax (4 threads/query); Ps overwritten in place ----
        {
            const int q = tid >> 2;
            const int r = tid & 3;
            float mx = -1e30f;
            #pragma unroll
            for (int t = 0; t < 16; t++) mx = fmaxf(mx, sm.Ps[q][r * 16 + t]);
            mx = fmaxf(mx, __shfl_xor_sync(0xffffffffu, mx, 1));
            mx = fmaxf(mx, __shfl_xor_sync(0xffffffffu, mx, 2));
            const float m_old = sm.m_s[q];
            const float m_new = fmaxf(m_old, mx);
            float sum = 0.f;
            #pragma unroll
            for (int t = 0; t < 16; t++) {
                const float p = __expf(sm.Ps[q][r * 16 + t] - m_new);
                sum += p;
                uint32_t ph, pl;
                split_tf32(p, ph, pl);
                sm.Ps[q][r * 16 + t] = __uint_as_float(ph);
                sm.Pl[q][r * 16 + t] = __uint_as_float(pl);
            }
            sum += __shfl_xor_sync(0xffffffffu, sum, 1);
            sum += __shfl_xor_sync(0xffffffffu, sum, 2);
            if (r == 0) {
                const float alpha = __expf(m_old - m_new);
                sm.m_s[q] = m_new;
                sm.l_s[q] = sm.l_s[q] * alpha + sum;
                sm.alpha_s[q] = alpha;
            }
        }
        __syncthreads();

        // ---- O = O*alpha + P V (64x64x64), 3xtf32 ----
        #pragma unroll
        for (int mf = 0; mf < 2; mf++) {
            const int r0 = warp_m * 32 + mf * 16 + (lane >> 2);
            const float a0 = sm.alpha_s[r0];
            const float a1 = sm.alpha_s[r0 + 8];
            #pragma unroll
            for (int nf = 0; nf < 2; nf++) {
                o[mf][nf][0] *= a0; o[mf][nf][1] *= a0;
                o[mf][nf][2] *= a1; o[mf][nf][3] *= a1;
            }
        }
        #pragma unroll
        for (int k8 = 0; k8 < 8; k8++) {
            uint32_t aH[2][4], aL[2][4];
            #pragma unroll
            for (int mf = 0; mf < 2; mf++) {
                const int qrow = warp_m * 32 + mf * 16 + lm_row;
                const uint32_t foff = 4u * (qrow * 68 + (k8 * 2 + lm_csel) * 4);
                LDSM_X4(aH[mf][0], aH[mf][1], aH[mf][2], aH[mf][3], ps_base + foff);
                LDSM_X4(aL[mf][0], aL[mf][1], aL[mf][2], aL[mf][3], pl_base + foff);
            }
            const int kk = k8 * 8;
            #pragma unroll
            for (int nf = 0; nf < 2; nf++) {
                const int d = warp_n * 16 + nf * 8 + bf_n;
                uint32_t bh0, bl0, bh1, bl1;
                split_tf32(sm.Vs[kk + bf_k][d], bh0, bl0);
                split_tf32(sm.Vs[kk + 4 + bf_k][d], bh1, bl1);
                #pragma unroll
                for (int mf = 0; mf < 2; mf++) {
                    MMA_TF32(o[mf][nf], aH[mf][0], aH[mf][1], aH[mf][2], aH[mf][3], bh0, bh1);
                    MMA_TF32(o[mf][nf], aH[mf][0], aH[mf][1], aH[mf][2], aH[mf][3], bl0, bl1);
                    MMA_TF32(o[mf][nf], aL[mf][0], aL[mf][1], aL[mf][2], aL[mf][3], bh0, bh1);
                }
            }
        }
    }

    #pragma unroll
    for (int mf = 0; mf < 2; mf++) {
        const int r0 = warp_m * 32 + mf * 16 + (lane >> 2);
        const float inv0 = 1.f / sm.l_s[r0];
        const float inv1 = 1.f / sm.l_s[r0 + 8];
        #pragma unroll
        for (int nf = 0; nf < 2; nf++) {
            const int col = h * HDIM + warp_n * 16 + nf * 8 + 2 * (lane & 3);
            *(float2*)(out + (size_t)(qrow0 + r0) * DMODEL + col) =
                make_float2(o[mf][nf][0] * inv0, o[mf][nf][1] * inv0);
            *(float2*)(out + (size_t)(qrow0 + r0 + 8) * DMODEL + col) =
                make_float2(o[mf][nf][2] * inv1, o[mf][nf][3] * inv1);
        }
    }
}

// ---------------------------------------------------------------------------
extern "C" void kernel_launch(void* const* d_in, const int* in_sizes, int n_in,
                              void* d_out, int out_size) {
    const float* x      = (const float*)d_in[0];   // [4096,1024]
    const float* w_qkv  = (const float*)d_in[1];   // [1024,3072]
    const float* w_out  = (const float*)d_in[2];   // [1024,1024]
    float* out = (float*)d_out;                    // [4096,1024]

    float *qkv, *attn;
    cudaGetSymbolAddress((void**)&qkv, g_qkv);
    cudaGetSymbolAddress((void**)&attn, g_attn);

    const int gemm_smem = SM_TOTAL_U32 * 4;
    cudaFuncSetAttribute(gemm_3xtf32, cudaFuncAttributeMaxDynamicSharedMemorySize,
                         gemm_smem);
    cudaFuncSetAttribute(attn_mma, cudaFuncAttributeMaxDynamicSharedMemorySize,
                         (int)sizeof(AttnSmem2));

    // 1) qkv = x @ w_qkv   [4096,1024]x[1024,3072]
    gemm_3xtf32<<<dim3(D3 / 128, SEQ / 128), 256, gemm_smem>>>(x, w_qkv, qkv,
                                                               SEQ, D3, DMODEL);
    // 2) sliding-window attention (tensor-core)
    attn_mma<<<dim3(8, NCHUNK, NHEAD), 256, sizeof(AttnSmem2)>>>(qkv, attn);
    // 3) out = attn @ w_out   [4096,1024]x[1024,1024]
    gemm_3xtf32<<<dim3(DMODEL / 128, SEQ / 128), 256, gemm_smem>>>(attn, w_out, out,
                                                                   SEQ, DMODEL, DMODEL);
}